// round 9
// baseline (speedup 1.0000x reference)
#include <cuda_runtime.h>
#include <mma.h>
#include <cstdint>

using namespace nvcuda;

#define N_NODES 100000
#define N_EDGES 1600000
#define HID 128
#define NUM_LAYERS 10
#define NUM_GRAPHS 64
#define NUM_CLASSES 2

// ---------------- scratch (device globals; no runtime allocation) ----------------
// g_h padded by 128 rows so tail-block wmma fragment loads never fault (pad is .bss zeros)
__device__ __align__(16) float g_x[(size_t)N_NODES * HID];
__device__ __align__(16) float g_h[(size_t)(N_NODES + 128) * HID];
__device__ int   g_deg[N_NODES];
__device__ int   g_rowptr[N_NODES + 1];
__device__ int   g_fill[N_NODES];
__device__ int   g_ssrc[N_EDGES];
__device__ int   g_bsums[256];
__device__ __align__(16) float g_pool[NUM_GRAPHS * HID];
__device__ float g_cnt[NUM_GRAPHS];
__device__ __align__(16) float g_cls[NUM_GRAPHS * HID];

// ---------------- CSR build ----------------
__global__ void zero_kernel() {
    int i = blockIdx.x * blockDim.x + threadIdx.x;
    if (i < N_NODES) g_deg[i] = 0;
    if (i < NUM_GRAPHS * HID) g_pool[i] = 0.f;
    if (i < NUM_GRAPHS) g_cnt[i] = 0.f;
}

__global__ void hist_kernel(const int* __restrict__ dst) {
    int e = blockIdx.x * blockDim.x + threadIdx.x;
    if (e < N_EDGES) atomicAdd(&g_deg[dst[e]], 1);
}

__global__ void scan1_kernel() {
    __shared__ int s[512];
    int tid = threadIdx.x;
    int i = blockIdx.x * 512 + tid;
    int v = (i < N_NODES) ? g_deg[i] : 0;
    s[tid] = v;
    __syncthreads();
    for (int off = 1; off < 512; off <<= 1) {
        int add = (tid >= off) ? s[tid - off] : 0;
        __syncthreads();
        s[tid] += add;
        __syncthreads();
    }
    if (i < N_NODES) g_rowptr[i] = s[tid] - v;
    if (tid == 511) g_bsums[blockIdx.x] = s[511];
}

__global__ void scan2_kernel(int nblk) {
    __shared__ int s[256];
    int tid = threadIdx.x;
    int v = (tid < nblk) ? g_bsums[tid] : 0;
    s[tid] = v;
    __syncthreads();
    for (int off = 1; off < 256; off <<= 1) {
        int add = (tid >= off) ? s[tid - off] : 0;
        __syncthreads();
        s[tid] += add;
        __syncthreads();
    }
    if (tid < nblk) g_bsums[tid] = s[tid] - v;
}

__global__ void scan3_kernel() {
    int i = blockIdx.x * blockDim.x + threadIdx.x;
    if (i < N_NODES) {
        int rp = g_rowptr[i] + g_bsums[i >> 9];
        g_rowptr[i] = rp;
        g_fill[i] = rp;
    }
    if (i == 0) g_rowptr[N_NODES] = N_EDGES;
}

__global__ void scatter_kernel(const int* __restrict__ src,
                               const int* __restrict__ dst) {
    int e = blockIdx.x * blockDim.x + threadIdx.x;
    if (e < N_EDGES) {
        int d = dst[e];
        int p = atomicAdd(&g_fill[d], 1);
        g_ssrc[p] = src[e];
    }
}

// ---------------- per-layer aggregation: h[v] = (1+eps)*x[v] + sum_in x[u] --------
__global__ void aggr_kernel(const float* __restrict__ xin_ext,
                            const float* __restrict__ eps, int layer, int use_gx) {
    int gw = (blockIdx.x * blockDim.x + threadIdx.x) >> 5;
    int lane = threadIdx.x & 31;
    if (gw >= N_NODES) return;
    const float* x = use_gx ? g_x : xin_ext;
    float ep1 = 1.0f + eps[layer];
    const float4* xv = (const float4*)x;
    float4 b = __ldg(&xv[(size_t)gw * 32 + lane]);
    float4 a0 = make_float4(b.x * ep1, b.y * ep1, b.z * ep1, b.w * ep1);
    float4 a1 = make_float4(0.f, 0.f, 0.f, 0.f);
    float4 a2 = a1, a3 = a1;
    int s = g_rowptr[gw], e = g_rowptr[gw + 1];
    int i = s;
    for (; i + 4 <= e; i += 4) {
        int s0 = g_ssrc[i], s1 = g_ssrc[i + 1], s2 = g_ssrc[i + 2], s3 = g_ssrc[i + 3];
        float4 v0 = __ldg(&xv[(size_t)s0 * 32 + lane]);
        float4 v1 = __ldg(&xv[(size_t)s1 * 32 + lane]);
        float4 v2 = __ldg(&xv[(size_t)s2 * 32 + lane]);
        float4 v3 = __ldg(&xv[(size_t)s3 * 32 + lane]);
        a0.x += v0.x; a0.y += v0.y; a0.z += v0.z; a0.w += v0.w;
        a1.x += v1.x; a1.y += v1.y; a1.z += v1.z; a1.w += v1.w;
        a2.x += v2.x; a2.y += v2.y; a2.z += v2.z; a2.w += v2.w;
        a3.x += v3.x; a3.y += v3.y; a3.z += v3.z; a3.w += v3.w;
    }
    for (; i < e; i++) {
        int s0 = g_ssrc[i];
        float4 v0 = __ldg(&xv[(size_t)s0 * 32 + lane]);
        a1.x += v0.x; a1.y += v0.y; a1.z += v0.z; a1.w += v0.w;
    }
    a0.x += a1.x + a2.x + a3.x;
    a0.y += a1.y + a2.y + a3.y;
    a0.z += a1.z + a2.z + a3.z;
    a0.w += a1.w + a2.w + a3.w;
    ((float4*)g_h)[(size_t)gw * 32 + lane] = a0;
}

// ================= wmma 3xTF32 fused MLP =========================================
// 128 threads = 4 independent warps; each warp owns 16 rows of a 64-row tile.
// 3xTF32: v = hi + lo (both tf32); A*B ~= Ahi*Bhi + Alo*Bhi + Ahi*Blo  (fp32-grade).
#define WM_BM 64
#define TS_LD 136   // smem leading dim (mult of 8)

typedef wmma::fragment<wmma::matrix_a, 16, 16, 8, wmma::precision::tf32, wmma::row_major> AFrag;
typedef wmma::fragment<wmma::matrix_b, 16, 16, 8, wmma::precision::tf32, wmma::row_major> BFrag;
typedef wmma::fragment<wmma::accumulator, 16, 16, 8, float> CFrag;

// one fused GEMM stage: c[0..7] += split(A from src) @ split(W)
__device__ __forceinline__ void gemm_3xtf32(CFrag* c, const float* __restrict__ A,
                                            int lda, const float* __restrict__ W) {
#pragma unroll
    for (int nt = 0; nt < 8; nt++) wmma::fill_fragment(c[nt], 0.f);
#pragma unroll
    for (int k = 0; k < 16; k++) {
        AFrag af, ahi, alo;
        wmma::load_matrix_sync(af, A + (size_t)k * 8, lda);
#pragma unroll
        for (int i = 0; i < af.num_elements; i++) {
            float v = af.x[i];
            float h = wmma::__float_to_tf32(v);
            ahi.x[i] = h;
            alo.x[i] = wmma::__float_to_tf32(v - h);
        }
#pragma unroll
        for (int nt = 0; nt < 8; nt++) {
            BFrag bf, bhi, blo;
            wmma::load_matrix_sync(bf, W + (size_t)(k * 8) * HID + nt * 16, HID);
#pragma unroll
            for (int i = 0; i < bf.num_elements; i++) {
                float v = bf.x[i];
                float h = wmma::__float_to_tf32(v);
                bhi.x[i] = h;
                blo.x[i] = wmma::__float_to_tf32(v - h);
            }
            wmma::mma_sync(c[nt], ahi, bhi, c[nt]);
            wmma::mma_sync(c[nt], alo, bhi, c[nt]);
            wmma::mma_sync(c[nt], ahi, blo, c[nt]);
        }
    }
}

__global__ void __launch_bounds__(128, 4)
mlp_wmma_kernel(const float* __restrict__ xin_ext,
                const float* __restrict__ W1, const float* __restrict__ b1,
                const float* __restrict__ W2, const float* __restrict__ b2,
                int add_h, int use_gx) {
    __shared__ __align__(32) float Ts[4 * 16 * TS_LD];   // 34.8 KB

    const float* xin = use_gx ? g_x : xin_ext;
    int w = threadIdx.x >> 5;
    int lane = threadIdx.x & 31;
    int row0 = blockIdx.x * WM_BM;
    int wrow = row0 + w * 16;               // may exceed N_NODES; g_h padded
    float* ts = Ts + w * 16 * TS_LD;

    CFrag c[8];

    // ---- GEMM1: C = split(h) @ split(W1)
    gemm_3xtf32(c, g_h + (size_t)wrow * HID, HID, W1);

#pragma unroll
    for (int nt = 0; nt < 8; nt++)
        wmma::store_matrix_sync(ts + nt * 16, c[nt], TS_LD, wmma::mem_row_major);
    __syncwarp();
    for (int idx = lane; idx < 16 * 128; idx += 32) {
        int r = idx >> 7, cc = idx & 127;
        float v = ts[r * TS_LD + cc] + __ldg(&b1[cc]);
        ts[r * TS_LD + cc] = fmaxf(v, 0.f);
    }
    __syncwarp();

    // ---- GEMM2: C = split(T) @ split(W2)
    gemm_3xtf32(c, ts, TS_LD, W2);

#pragma unroll
    for (int nt = 0; nt < 8; nt++)
        wmma::store_matrix_sync(ts + nt * 16, c[nt], TS_LD, wmma::mem_row_major);
    __syncwarp();

    // ---- epilogue: out = relu(C + b2 [+ h]) + xin
    for (int idx = lane; idx < 16 * 128; idx += 32) {
        int r = idx >> 7, cc = idx & 127;
        int grow = wrow + r;
        if (grow < N_NODES) {
            size_t base = (size_t)grow * HID + cc;
            float v = ts[r * TS_LD + cc] + __ldg(&b2[cc]);
            if (add_h) v += g_h[base];
            g_x[base] = fmaxf(v, 0.f) + xin[base];
        }
    }
}

// ---------------- mean pool over sorted batch ----------------
#define POOL_CHUNK 256
__global__ void pool_kernel(const int* __restrict__ batch) {
    int d = threadIdx.x;  // 128
    int n0 = blockIdx.x * POOL_CHUNK;
    int n1 = n0 + POOL_CHUNK; if (n1 > N_NODES) n1 = N_NODES;
    int cur = batch[n0];
    float local = 0.f;
    for (int n = n0; n < n1; n++) {
        int b = batch[n];
        if (b != cur) {
            atomicAdd(&g_pool[cur * HID + d], local);
            local = 0.f; cur = b;
        }
        local += g_x[(size_t)n * HID + d];
    }
    atomicAdd(&g_pool[cur * HID + d], local);
    if (d == 0) {
        int c2 = batch[n0];
        float cl = 0.f;
        for (int n = n0; n < n1; n++) {
            int b = batch[n];
            if (b != c2) { atomicAdd(&g_cnt[c2], cl); cl = 0.f; c2 = b; }
            cl += 1.f;
        }
        atomicAdd(&g_cnt[c2], cl);
    }
}

// ---------------- classifier ----------------
__global__ void cls1_kernel(const float* __restrict__ Wc1,
                            const float* __restrict__ bc1) {
    __shared__ float Ps[128];
    int g = blockIdx.x;
    int t = threadIdx.x;
    float inv = 1.f / fmaxf(g_cnt[g], 1.f);
    Ps[t] = g_pool[g * HID + t] * inv;
    __syncthreads();
    float s = bc1[t];
#pragma unroll 4
    for (int k = 0; k < 128; k++) s += Ps[k] * __ldg(&Wc1[k * 128 + t]);
    g_cls[g * HID + t] = fmaxf(s, 0.f);
}

__global__ void cls2_kernel(const float* __restrict__ Wc2,
                            const float* __restrict__ bc2,
                            float* __restrict__ out) {
    int t = threadIdx.x;
    int g = t >> 1, c = t & 1;
    float s = bc2[c];
#pragma unroll 4
    for (int k = 0; k < 128; k++) s += g_cls[g * HID + k] * __ldg(&Wc2[k * 2 + c]);
    out[t] = s;
}

// ---------------- launch (pure kernel launches — graph-capture safe) -------------
extern "C" void kernel_launch(void* const* d_in, const int* in_sizes, int n_in,
                              void* d_out, int out_size) {
    const float* x     = (const float*)d_in[0];
    const int*   ei    = (const int*)d_in[1];     // int32 (JAX x64 disabled)
    const int*   batch = (const int*)d_in[2];     // int32
    const float* eps   = (const float*)d_in[3];
    const float* W1    = (const float*)d_in[4];
    const float* b1    = (const float*)d_in[5];
    const float* W2    = (const float*)d_in[6];
    const float* b2    = (const float*)d_in[7];
    const float* Wc1   = (const float*)d_in[8];
    const float* bc1   = (const float*)d_in[9];
    const float* Wc2   = (const float*)d_in[10];
    const float* bc2   = (const float*)d_in[11];
    const int* src = ei;
    const int* dst = ei + N_EDGES;

    const int nblk_scan = (N_NODES + 511) / 512;            // 196
    const int nblk_mlp  = (N_NODES + WM_BM - 1) / WM_BM;    // 1563

    zero_kernel<<<(N_NODES + 255) / 256, 256>>>();
    hist_kernel<<<(N_EDGES + 255) / 256, 256>>>(dst);
    scan1_kernel<<<nblk_scan, 512>>>();
    scan2_kernel<<<1, 256>>>(nblk_scan);
    scan3_kernel<<<(N_NODES + 255) / 256, 256>>>();
    scatter_kernel<<<(N_EDGES + 255) / 256, 256>>>(src, dst);

    for (int i = 0; i < NUM_LAYERS; i++) {
        int use_gx = (i > 0) ? 1 : 0;
        aggr_kernel<<<(N_NODES + 7) / 8, 256>>>(x, eps, i, use_gx);
        mlp_wmma_kernel<<<nblk_mlp, 128>>>(
            x,
            W1 + (size_t)i * HID * HID, b1 + (size_t)i * HID,
            W2 + (size_t)i * HID * HID, b2 + (size_t)i * HID,
            (i > 0) ? 1 : 0, use_gx);
    }

    pool_kernel<<<(N_NODES + POOL_CHUNK - 1) / POOL_CHUNK, 128>>>(batch);
    cls1_kernel<<<NUM_GRAPHS, 128>>>(Wc1, bc1);
    cls2_kernel<<<1, 128>>>(Wc2, bc2, (float*)d_out);
}